// round 5
// baseline (speedup 1.0000x reference)
#include <cuda_runtime.h>
#include <cuda_fp16.h>
#include <cstdint>

// ---------------------------------------------------------------------------
// GCN, fp16 data path (10-bit mantissa == tf32, so no precision loss vs tf32):
//   xh = fp16(x * out_norm)                     [convert kernel]
//   agg1 = fp16(Agg(xh) * in_norm)              [gather-only, 256B rows]
//   h1 = fp16(relu(agg1 @ w1 + b1) * out_norm)  [fp16 mma GEMM, fused epilogue]
//   agg2 = fp16(Agg(h1) * in_norm)
//   h2 = fp16(relu(agg2 @ w2 + b2))
//   h3 = fp16(relu(h2 @ wm1 + bm1))
//   out = fp32(h3 @ wm2 + bm2)
// CSR built per-launch: histogram -> single-block scan -> bucket scatter.
// ---------------------------------------------------------------------------

#define N_MAX 100000
#define E_MAX 3200000

__device__ int    g_deg_in[N_MAX];
__device__ int    g_deg_out[N_MAX];
__device__ int    g_row_ptr[N_MAX + 1];
__device__ int    g_cursor[N_MAX];
__device__ int    g_sorted_src[E_MAX];
__device__ float  g_out_norm[N_MAX];
__device__ float  g_in_norm[N_MAX];
__device__ __half g_xh[(size_t)N_MAX * 128];
__device__ __half g_aggh[(size_t)N_MAX * 128];
__device__ __half g_hh[(size_t)N_MAX * 128];
__device__ __half g_h3h[(size_t)N_MAX * 256];

// ---------------------------------------------------------------------------
__global__ void zero_deg_kernel(int n, int* deg_in, int* deg_out) {
    int i = blockIdx.x * blockDim.x + threadIdx.x;
    if (i < n) { deg_in[i] = 0; deg_out[i] = 0; }
}

__global__ void hist_kernel(int e, const int* __restrict__ src,
                            const int* __restrict__ dst,
                            int* deg_in, int* deg_out) {
    int i = blockIdx.x * blockDim.x + threadIdx.x;
    if (i < e) {
        atomicAdd(&deg_out[src[i]], 1);
        atomicAdd(&deg_in[dst[i]], 1);
    }
}

// Single-block exclusive scan (chunked, shfl-based).
__global__ void scan_kernel(int n, const int* __restrict__ deg, int* __restrict__ row_ptr) {
    __shared__ int wsum[32];
    __shared__ int s_carry;
    const int tid = threadIdx.x;
    const int lane = tid & 31;
    const int wid = tid >> 5;
    if (tid == 0) s_carry = 0;
    __syncthreads();
    for (int base = 0; base < n; base += 1024) {
        int idx = base + tid;
        int v = (idx < n) ? deg[idx] : 0;
        int x = v;
        #pragma unroll
        for (int o = 1; o < 32; o <<= 1) {
            int t = __shfl_up_sync(0xffffffffu, x, o);
            if (lane >= o) x += t;
        }
        if (lane == 31) wsum[wid] = x;
        __syncthreads();
        if (wid == 0) {
            int y = wsum[lane];
            #pragma unroll
            for (int o = 1; o < 32; o <<= 1) {
                int t = __shfl_up_sync(0xffffffffu, y, o);
                if (lane >= o) y += t;
            }
            wsum[lane] = y;
        }
        __syncthreads();
        int wofs = (wid > 0) ? wsum[wid - 1] : 0;
        int incl = x + wofs;
        int carry = s_carry;
        if (idx < n) row_ptr[idx] = carry + incl - v;  // exclusive
        __syncthreads();
        if (tid == 1023) s_carry = carry + wsum[31];
        __syncthreads();
    }
    if (threadIdx.x == 0) row_ptr[n] = s_carry;
}

__global__ void finalize_kernel(int n, const int* __restrict__ deg_out,
                                const int* __restrict__ deg_in,
                                const int* __restrict__ row_ptr,
                                float* out_norm, float* in_norm, int* cursor) {
    int i = blockIdx.x * blockDim.x + threadIdx.x;
    if (i < n) {
        out_norm[i] = rsqrtf((float)max(deg_out[i], 1));
        in_norm[i]  = rsqrtf((float)max(deg_in[i], 1));
        cursor[i]   = row_ptr[i];
    }
}

__global__ void scatter_kernel(int e, const int* __restrict__ src,
                               const int* __restrict__ dst,
                               int* cursor, int* __restrict__ sorted_src) {
    int i = blockIdx.x * blockDim.x + threadIdx.x;
    if (i < e) {
        int d = dst[i];
        int pos = atomicAdd(&cursor[d], 1);
        sorted_src[pos] = src[i];
    }
}

// xh[i, :] = fp16(x[i, :] * out_norm[i]); one thread per 4 features.
__global__ void convert_x_kernel(int n, const float* __restrict__ x,
                                 const float* __restrict__ onorm,
                                 __half* __restrict__ xh) {
    int idx = blockIdx.x * blockDim.x + threadIdx.x;   // 0 .. n*32-1
    if (idx >= n * 32) return;
    int row = idx >> 5;
    float s = onorm[row];
    float4 v = *reinterpret_cast<const float4*>(x + (size_t)idx * 4);
    __half2 o0 = __floats2half2_rn(v.x * s, v.y * s);
    __half2 o1 = __floats2half2_rn(v.z * s, v.w * s);
    uint2 ov;
    ov.x = *reinterpret_cast<uint32_t*>(&o0);
    ov.y = *reinterpret_cast<uint32_t*>(&o1);
    *reinterpret_cast<uint2*>(xh + (size_t)idx * 4) = ov;
}

// ---------------------------------------------------------------------------
// fp16 gather aggregation: one warp per node; lane l owns features [4l, 4l+4).
// out = fp16(sum_{in-edges} feat[src] * in_norm[node])
__global__ void agg_h_kernel(int n, const __half* __restrict__ feat,
                             const int* __restrict__ row_ptr,
                             const int* __restrict__ srcs,
                             const float* __restrict__ inorm,
                             __half* __restrict__ out) {
    int warp = (blockIdx.x * blockDim.x + threadIdx.x) >> 5;
    if (warp >= n) return;
    const int lane = threadIdx.x & 31;
    const int beg = row_ptr[warp];
    const int end = row_ptr[warp + 1];
    float a0 = 0.f, a1 = 0.f, a2 = 0.f, a3 = 0.f;
    for (int i = beg; i < end; i += 32) {
        int cnt = min(32, end - i);
        int s = 0;
        if (lane < cnt) s = __ldg(srcs + i + lane);
        for (int j = 0; j < cnt; j++) {
            int sj = __shfl_sync(0xffffffffu, s, j);
            uint2 v = *reinterpret_cast<const uint2*>(feat + (size_t)sj * 128 + lane * 4);
            __half2 h0 = *reinterpret_cast<__half2*>(&v.x);
            __half2 h1 = *reinterpret_cast<__half2*>(&v.y);
            float2 f0 = __half22float2(h0);
            float2 f1 = __half22float2(h1);
            a0 += f0.x; a1 += f0.y; a2 += f1.x; a3 += f1.y;
        }
    }
    float iw = inorm[warp];
    __half2 o0 = __floats2half2_rn(a0 * iw, a1 * iw);
    __half2 o1 = __floats2half2_rn(a2 * iw, a3 * iw);
    uint2 ov;
    ov.x = *reinterpret_cast<uint32_t*>(&o0);
    ov.y = *reinterpret_cast<uint32_t*>(&o1);
    *reinterpret_cast<uint2*>(out + (size_t)warp * 128 + lane * 4) = ov;
}

// ---------------------------------------------------------------------------
// fp16 tensor-core GEMM via mma.sync.m16n8k16 (fp32 accumulate).
// A fp16 [M x K] row-major; W fp32 [K x ldn] converted to fp16 + transposed in
// SMEM; block tile 128x64x32; 8 warps = 4(M) x 2(N); warp tile 32x32.
// Epilogue: +bias, optional relu, optional per-row scale, out fp16 or fp32.
// ---------------------------------------------------------------------------
__device__ __forceinline__ void mma_f16(float c[4], uint32_t a0, uint32_t a1,
                                        uint32_t a2, uint32_t a3,
                                        uint32_t b0, uint32_t b1) {
    asm volatile(
        "mma.sync.aligned.m16n8k16.row.col.f32.f16.f16.f32 "
        "{%0,%1,%2,%3}, {%4,%5,%6,%7}, {%8,%9}, {%0,%1,%2,%3};\n"
        : "+f"(c[0]), "+f"(c[1]), "+f"(c[2]), "+f"(c[3])
        : "r"(a0), "r"(a1), "r"(a2), "r"(a3), "r"(b0), "r"(b1));
}

template <bool RELU, bool PSCALE, bool OUTH>
__global__ __launch_bounds__(256) void gemm_f16_kernel(
        int M, int K, int ldn,
        const __half* __restrict__ A,
        const float* __restrict__ W,
        const float* __restrict__ bias,
        const float* __restrict__ pscale,
        void* __restrict__ Cout) {
    constexpr int BM = 128, BN = 64, BK = 32;
    constexpr int ASTR = BK + 8;   // halves; 80B row stride, conflict-free frags
    constexpr int WSTR = BK + 8;   // Wt is [BN][BK] (transposed), same stride
    __shared__ __half As[BM * ASTR];
    __shared__ __half Wt[BN * WSTR];

    const int tid = threadIdx.x;
    const int lane = tid & 31;
    const int wid = tid >> 5;
    const int g = lane >> 2;       // 0..7
    const int tig = lane & 3;      // 0..3
    const int warpM = (wid & 3) * 32;
    const int warpN = (wid >> 2) * 32;
    const int rowBase = blockIdx.x * BM;
    const int nBase = blockIdx.y * BN;

    uint2  ra[4];                  // A stage: 4 x (4 halves)
    float4 rw[2];                  // W stage: 2 x (4 floats)

    auto loadA = [&](int kb) {
        #pragma unroll
        for (int i = 0; i < 4; i++) {
            int id = tid + i * 256;        // 0..1023
            int row = id >> 3;             // 0..127
            int c4 = (id & 7) * 4;         // halves 0..28
            int grow = rowBase + row;
            if (grow < M)
                ra[i] = *reinterpret_cast<const uint2*>(A + (size_t)grow * K + kb + c4);
            else
                ra[i] = make_uint2(0u, 0u);
        }
    };
    auto loadW = [&](int kb) {
        #pragma unroll
        for (int i = 0; i < 2; i++) {
            int id = tid + i * 256;        // 0..511
            int k = id >> 4;               // 0..31
            int c4 = (id & 15) * 4;        // 0..60
            rw[i] = *reinterpret_cast<const float4*>(W + (size_t)(kb + k) * ldn + nBase + c4);
        }
    };
    auto storeA = [&]() {
        #pragma unroll
        for (int i = 0; i < 4; i++) {
            int id = tid + i * 256;
            int row = id >> 3;
            int c4 = (id & 7) * 4;
            *reinterpret_cast<uint2*>(&As[row * ASTR + c4]) = ra[i];
        }
    };
    auto storeW = [&]() {
        #pragma unroll
        for (int i = 0; i < 2; i++) {
            int id = tid + i * 256;
            int k = id >> 4;
            int c4 = (id & 15) * 4;
            Wt[(c4 + 0) * WSTR + k] = __float2half_rn(rw[i].x);
            Wt[(c4 + 1) * WSTR + k] = __float2half_rn(rw[i].y);
            Wt[(c4 + 2) * WSTR + k] = __float2half_rn(rw[i].z);
            Wt[(c4 + 3) * WSTR + k] = __float2half_rn(rw[i].w);
        }
    };

    float acc[2][4][4];
    #pragma unroll
    for (int m = 0; m < 2; m++)
        #pragma unroll
        for (int n = 0; n < 4; n++)
            #pragma unroll
            for (int q = 0; q < 4; q++) acc[m][n][q] = 0.f;

    loadA(0);
    loadW(0);

    for (int kb = 0; kb < K; kb += BK) {
        storeA();
        storeW();
        __syncthreads();
        if (kb + BK < K) { loadA(kb + BK); loadW(kb + BK); }

        #pragma unroll
        for (int ks = 0; ks < BK; ks += 16) {
            uint32_t af[2][4];
            #pragma unroll
            for (int m = 0; m < 2; m++) {
                int r0 = warpM + m * 16 + g;
                int r1 = r0 + 8;
                af[m][0] = *reinterpret_cast<const uint32_t*>(&As[r0 * ASTR + ks + tig * 2]);
                af[m][1] = *reinterpret_cast<const uint32_t*>(&As[r1 * ASTR + ks + tig * 2]);
                af[m][2] = *reinterpret_cast<const uint32_t*>(&As[r0 * ASTR + ks + tig * 2 + 8]);
                af[m][3] = *reinterpret_cast<const uint32_t*>(&As[r1 * ASTR + ks + tig * 2 + 8]);
            }
            uint32_t bf[4][2];
            #pragma unroll
            for (int n = 0; n < 4; n++) {
                int cn = warpN + n * 8 + g;
                bf[n][0] = *reinterpret_cast<const uint32_t*>(&Wt[cn * WSTR + ks + tig * 2]);
                bf[n][1] = *reinterpret_cast<const uint32_t*>(&Wt[cn * WSTR + ks + tig * 2 + 8]);
            }
            #pragma unroll
            for (int m = 0; m < 2; m++)
                #pragma unroll
                for (int n = 0; n < 4; n++)
                    mma_f16(acc[m][n], af[m][0], af[m][1], af[m][2], af[m][3],
                            bf[n][0], bf[n][1]);
        }
        __syncthreads();
    }

    // Epilogue
    #pragma unroll
    for (int n = 0; n < 4; n++) {
        int col = nBase + warpN + n * 8 + tig * 2;
        float bv0 = bias[col];
        float bv1 = bias[col + 1];
        #pragma unroll
        for (int m = 0; m < 2; m++) {
            #pragma unroll
            for (int half = 0; half < 2; half++) {
                int row = rowBase + warpM + m * 16 + g + half * 8;
                if (row >= M) continue;
                float sc = PSCALE ? pscale[row] : 1.f;
                float o0 = acc[m][n][half * 2 + 0] + bv0;
                float o1 = acc[m][n][half * 2 + 1] + bv1;
                if (RELU) { o0 = fmaxf(o0, 0.f); o1 = fmaxf(o1, 0.f); }
                o0 *= sc; o1 *= sc;
                if (OUTH) {
                    __half2 o = __floats2half2_rn(o0, o1);
                    *reinterpret_cast<__half2*>((__half*)Cout + (size_t)row * ldn + col) = o;
                } else {
                    *reinterpret_cast<float2*>((float*)Cout + (size_t)row * ldn + col) =
                        make_float2(o0, o1);
                }
            }
        }
    }
}

// ---------------------------------------------------------------------------
extern "C" void kernel_launch(void* const* d_in, const int* in_sizes, int n_in,
                              void* d_out, int out_size) {
    const float* x   = (const float*)d_in[0];
    const int*   src = (const int*)d_in[1];
    const int*   dst = (const int*)d_in[2];
    const float* w1  = (const float*)d_in[3];
    const float* b1  = (const float*)d_in[4];
    const float* w2  = (const float*)d_in[5];
    const float* b2  = (const float*)d_in[6];
    const float* wm1 = (const float*)d_in[7];
    const float* bm1 = (const float*)d_in[8];
    const float* wm2 = (const float*)d_in[9];
    const float* bm2 = (const float*)d_in[10];

    const int n = in_sizes[0] / 128;
    const int e = in_sizes[1];

    int *deg_in, *deg_out, *row_ptr, *cursor, *sorted_src;
    float *onorm, *inorm;
    __half *xh, *aggh, *hh, *h3h;
    cudaGetSymbolAddress((void**)&deg_in, g_deg_in);
    cudaGetSymbolAddress((void**)&deg_out, g_deg_out);
    cudaGetSymbolAddress((void**)&row_ptr, g_row_ptr);
    cudaGetSymbolAddress((void**)&cursor, g_cursor);
    cudaGetSymbolAddress((void**)&sorted_src, g_sorted_src);
    cudaGetSymbolAddress((void**)&onorm, g_out_norm);
    cudaGetSymbolAddress((void**)&inorm, g_in_norm);
    cudaGetSymbolAddress((void**)&xh, g_xh);
    cudaGetSymbolAddress((void**)&aggh, g_aggh);
    cudaGetSymbolAddress((void**)&hh, g_hh);
    cudaGetSymbolAddress((void**)&h3h, g_h3h);

    const int nb = (n + 255) / 256;
    const int eb = (e + 255) / 256;

    // --- CSR build ---
    zero_deg_kernel<<<nb, 256>>>(n, deg_in, deg_out);
    hist_kernel<<<eb, 256>>>(e, src, dst, deg_in, deg_out);
    scan_kernel<<<1, 1024>>>(n, deg_in, row_ptr);
    finalize_kernel<<<nb, 256>>>(n, deg_out, deg_in, row_ptr, onorm, inorm, cursor);
    scatter_kernel<<<eb, 256>>>(e, src, dst, cursor, sorted_src);

    // --- x -> fp16, prescaled by out_norm ---
    convert_x_kernel<<<(n * 32 + 255) / 256, 256>>>(n, x, onorm, xh);

    const int aggBlocks = (n + 7) / 8;  // 8 warps/block, warp per node
    const dim3 g2((n + 127) / 128, 2);
    const dim3 g4((n + 127) / 128, 4);
    const dim3 g1((n + 127) / 128, 1);

    // --- conv1 ---
    agg_h_kernel<<<aggBlocks, 256>>>(n, xh, row_ptr, sorted_src, inorm, aggh);
    gemm_f16_kernel<true, true, true><<<g2, 256>>>(n, 128, 128, aggh, w1, b1, onorm, hh);

    // --- conv2 ---
    agg_h_kernel<<<aggBlocks, 256>>>(n, hh, row_ptr, sorted_src, inorm, aggh);
    gemm_f16_kernel<true, false, true><<<g2, 256>>>(n, 128, 128, aggh, w2, b2, nullptr, hh);

    // --- MLP ---
    gemm_f16_kernel<true, false, true><<<g4, 256>>>(n, 128, 256, hh, wm1, bm1, nullptr, h3h);
    gemm_f16_kernel<false, false, false><<<g1, 256>>>(n, 256, 64, h3h, wm2, bm2, nullptr, d_out);
}